// round 3
// baseline (speedup 1.0000x reference)
#include <cuda_runtime.h>
#include <math.h>

#define BATCH 32
#define HGT 64
#define WID 64
#define CDIM 256
#define MTOT (BATCH*HGT*WID)   /* 131072 rows */
#define COUT_FULL 516

// ---------------- scratch (device globals: no allocation allowed) -----------
__device__ float g_q   [(size_t)MTOT*CDIM];   // clipped query
__device__ float g_c0  [(size_t)MTOT*CDIM];   // ping
__device__ float g_c1  [(size_t)MTOT*CDIM];   // pong
__device__ float g_acc [(size_t)MTOT*CDIM];   // context_all accumulator
__device__ float g_gates[(size_t)MTOT*4];     // clipped gates
__device__ float g_partial[BATCH*16*CDIM];    // deterministic mean stage 1
__device__ float g_mean[BATCH*CDIM];          // tanh(mean)

__device__ __forceinline__ float gelu_f(float x){
    return 0.5f*x*(1.0f+erff(x*0.70710678118654752440f));
}
__device__ __forceinline__ float clipf(float v, float lim){
    return fminf(fmaxf(v, -lim), lim);
}

// ---------------- 128x128x8 register-tiled SGEMM with fused epilogues -------
// MODE 0: A=x (ext), B=w_init (ldb=516), N=512. cols<256 -> g_q (clip 100),
//         cols>=256 -> g_c0 (context).
// MODE 1: A=g_acc, B=w_mod, N=256. out g_c0 = clip(v,100) * g_q  (q*modulator)
// MODE 2: A=g_c0,  B=w_proj, N=256. out ext (d_out) = v
template<int MODE>
__global__ __launch_bounds__(256)
void gemm_k(const float* __restrict__ Aext, const float* __restrict__ Bw,
            const float* __restrict__ bias, float* __restrict__ outext,
            int K, int ldb)
{
    const float* A = (MODE==0) ? Aext : (MODE==1 ? g_acc : g_c0);
    __shared__ float As[8][128];
    __shared__ float Bs[8][128];
    int t  = threadIdx.x;
    int tx = t & 15, ty = t >> 4;
    int row0 = blockIdx.y * 128;
    int col0 = blockIdx.x * 128;
    int arow = t >> 1;
    int akq  = (t & 1) << 2;
    int bkk  = t >> 5;
    int bc4  = (t & 31) << 2;
    const float* Ap = A  + (size_t)(row0 + arow) * K + akq;
    const float* Bp = Bw + (size_t)bkk * ldb + col0 + bc4;

    float acc[8][8];
    #pragma unroll
    for (int i=0;i<8;i++)
        #pragma unroll
        for (int j=0;j<8;j++) acc[i][j]=0.f;

    for (int k0 = 0; k0 < K; k0 += 8) {
        float4 av = *(const float4*)(Ap + k0);
        As[akq+0][arow]=av.x; As[akq+1][arow]=av.y;
        As[akq+2][arow]=av.z; As[akq+3][arow]=av.w;
        *(float4*)&Bs[bkk][bc4] = *(const float4*)(Bp + (size_t)k0*ldb);
        __syncthreads();
        #pragma unroll
        for (int kk=0; kk<8; kk++) {
            float4 a0 = *(float4*)&As[kk][ty*8];
            float4 a1 = *(float4*)&As[kk][ty*8+4];
            float4 b0 = *(float4*)&Bs[kk][tx*8];
            float4 b1 = *(float4*)&Bs[kk][tx*8+4];
            float a[8] = {a0.x,a0.y,a0.z,a0.w,a1.x,a1.y,a1.z,a1.w};
            float b[8] = {b0.x,b0.y,b0.z,b0.w,b1.x,b1.y,b1.z,b1.w};
            #pragma unroll
            for (int i=0;i<8;i++)
                #pragma unroll
                for (int j=0;j<8;j++)
                    acc[i][j] = fmaf(a[i], b[j], acc[i][j]);
        }
        __syncthreads();
    }

    #pragma unroll
    for (int i=0;i<8;i++) {
        int r = row0 + ty*8 + i;
        #pragma unroll
        for (int j=0;j<8;j++) {
            int c = col0 + tx*8 + j;
            float v = acc[i][j] + bias[c];
            if (MODE == 0) {
                if (c < CDIM)
                    g_q[(size_t)r*CDIM + c] = clipf(v, 100.f);
                else
                    g_c0[(size_t)r*CDIM + (c-CDIM)] = v;
            } else if (MODE == 1) {
                v = clipf(v, 100.f);
                g_c0[(size_t)r*CDIM + c] = v * g_q[(size_t)r*CDIM + c];
            } else {
                outext[(size_t)r*CDIM + c] = v;
            }
        }
    }
}

// ---------------- gates: last 4 columns of w_init, one warp per row ---------
__global__ __launch_bounds__(256)
void gates_k(const float* __restrict__ x, const float* __restrict__ w,
             const float* __restrict__ bias)
{
    int warp = (int)((blockIdx.x * blockDim.x + threadIdx.x) >> 5);
    int lane = threadIdx.x & 31;
    if (warp >= MTOT) return;
    const float* xr = x + (size_t)warp * CDIM;
    float s0=0.f, s1=0.f, s2=0.f, s3=0.f;
    #pragma unroll
    for (int k = lane; k < CDIM; k += 32) {
        float xv = xr[k];
        const float* wr = w + (size_t)k*COUT_FULL + 512;
        s0 = fmaf(xv, wr[0], s0);
        s1 = fmaf(xv, wr[1], s1);
        s2 = fmaf(xv, wr[2], s2);
        s3 = fmaf(xv, wr[3], s3);
    }
    #pragma unroll
    for (int o=16; o; o>>=1) {
        s0 += __shfl_down_sync(0xffffffffu, s0, o);
        s1 += __shfl_down_sync(0xffffffffu, s1, o);
        s2 += __shfl_down_sync(0xffffffffu, s2, o);
        s3 += __shfl_down_sync(0xffffffffu, s3, o);
    }
    if (lane == 0) {
        float* g = g_gates + (size_t)warp*4;
        g[0] = clipf(s0 + bias[512], 1.f);
        g[1] = clipf(s1 + bias[513], 1.f);
        g[2] = clipf(s2 + bias[514], 1.f);
        g[3] = clipf(s3 + bias[515], 1.f);
    }
}

// ---------------- depthwise conv SxS + gelu + gated accumulate --------------
// LEVEL 0: in g_c0 -> out g_c1, acc  = out*g0
// LEVEL 1: in g_c1 -> out g_c0, acc += out*g1
// LEVEL 2: in g_c0 -> out g_c1, acc += out*g2
// Tile: 16(H) x 8(W) spatial x 32 channels (8 float4). 256 threads,
// each thread: 1 float4-channel, 1 x-column, 4 y-outputs (register rolling).
template<int S, int LEVEL>
__global__ __launch_bounds__(256)
void dwconv_k(const float* __restrict__ kern)
{
    constexpr int P = S/2;
    constexpr int TH = 16, TW = 8, CF = 8;
    constexpr int HH = TH + S - 1, HW2 = TW + S - 1;
    const float* in = (LEVEL==1) ? g_c1 : g_c0;
    float* out      = (LEVEL==1) ? g_c0 : g_c1;

    __shared__ float4 sIn[HH*HW2][CF];
    __shared__ float4 sK[S*S][CF];

    int t  = threadIdx.x;
    int w0 = blockIdx.x * TW;
    int h0 = blockIdx.y * TH;
    int z  = blockIdx.z;
    int b  = z >> 3;
    int c0 = (z & 7) * 32;

    for (int i = t; i < S*S*CF; i += 256) {
        int f = i & 7, p = i >> 3;
        sK[p][f] = *(const float4*)(kern + p*CDIM + c0 + f*4);
    }
    for (int i = t; i < HH*HW2*CF; i += 256) {
        int f = i & 7, p = i >> 3;
        int hy = p / HW2, hx = p % HW2;
        int ih = h0 - P + hy, iw = w0 - P + hx;
        float4 v = make_float4(0.f,0.f,0.f,0.f);
        if (ih >= 0 && ih < HGT && iw >= 0 && iw < WID)
            v = *(const float4*)(in + ((size_t)((b*HGT+ih)*WID+iw))*CDIM + c0 + f*4);
        sIn[p][f] = v;
    }
    __syncthreads();

    int f  = t & 7;
    int ox = (t >> 3) & 7;
    int yq = t >> 6;          // 0..3, each handles 4 y rows

    float4 acc[4];
    #pragma unroll
    for (int i=0;i<4;i++) acc[i] = make_float4(0.f,0.f,0.f,0.f);

    #pragma unroll
    for (int kw = 0; kw < S; kw++) {
        float4 kv[S];
        #pragma unroll
        for (int kh = 0; kh < S; kh++) kv[kh] = sK[kh*S+kw][f];
        #pragma unroll
        for (int r = 0; r < 4 + S - 1; r++) {
            float4 iv = sIn[(yq*4 + r)*HW2 + ox + kw][f];
            #pragma unroll
            for (int kh = 0; kh < S; kh++) {
                int oy = r - kh;
                if (oy >= 0 && oy < 4) {
                    acc[oy].x = fmaf(iv.x, kv[kh].x, acc[oy].x);
                    acc[oy].y = fmaf(iv.y, kv[kh].y, acc[oy].y);
                    acc[oy].z = fmaf(iv.z, kv[kh].z, acc[oy].z);
                    acc[oy].w = fmaf(iv.w, kv[kh].w, acc[oy].w);
                }
            }
        }
    }

    #pragma unroll
    for (int oy = 0; oy < 4; oy++) {
        float4 v = acc[oy];
        v.x = gelu_f(v.x); v.y = gelu_f(v.y);
        v.z = gelu_f(v.z); v.w = gelu_f(v.w);
        size_t row = (size_t)(b*HGT + h0 + yq*4 + oy)*WID + (w0 + ox);
        size_t idx = row*CDIM + c0 + f*4;
        *(float4*)(out + idx) = v;
        float g = g_gates[row*4 + LEVEL];
        float4 a;
        if (LEVEL == 0) {
            a.x = v.x*g; a.y = v.y*g; a.z = v.z*g; a.w = v.w*g;
        } else {
            float4 prev = *(const float4*)(g_acc + idx);
            a.x = fmaf(v.x, g, prev.x); a.y = fmaf(v.y, g, prev.y);
            a.z = fmaf(v.z, g, prev.z); a.w = fmaf(v.w, g, prev.w);
        }
        *(float4*)(g_acc + idx) = a;
    }
}

// ---------------- spatial mean of final ctx (deterministic 2-stage) ---------
__global__ void mean_partial_k()
{
    int b = blockIdx.x, chunk = blockIdx.y;
    int c = threadIdx.x;
    const float* base = g_c1 + ((size_t)b*4096 + chunk*256)*CDIM + c;
    float s = 0.f;
    #pragma unroll 4
    for (int i = 0; i < 256; i++) s += base[(size_t)i*CDIM];
    g_partial[(b*16 + chunk)*CDIM + c] = s;
}
__global__ void mean_final_k()
{
    int b = blockIdx.x, c = threadIdx.x;
    float s = 0.f;
    #pragma unroll
    for (int i = 0; i < 16; i++) s += g_partial[(b*16 + i)*CDIM + c];
    g_mean[b*CDIM + c] = tanhf(s * (1.0f/4096.0f));
}
__global__ void add_global_k()
{
    int row = blockIdx.x;       // MTOT blocks
    int c   = threadIdx.x;      // 256
    int b   = row >> 12;        // row / 4096
    float g = g_gates[(size_t)row*4 + 3];
    size_t idx = (size_t)row*CDIM + c;
    g_acc[idx] = fmaf(g_mean[b*CDIM + c], g, g_acc[idx]);
}

// ---------------- launch ----------------------------------------------------
extern "C" void kernel_launch(void* const* d_in, const int* in_sizes, int n_in,
                              void* d_out, int out_size)
{
    const float* x      = (const float*)d_in[0];
    const float* w_init = (const float*)d_in[1];
    const float* b_init = (const float*)d_in[2];
    const float* k0     = (const float*)d_in[3];
    const float* k1     = (const float*)d_in[4];
    const float* k2     = (const float*)d_in[5];
    const float* w_mod  = (const float*)d_in[6];
    const float* b_mod  = (const float*)d_in[7];
    const float* w_proj = (const float*)d_in[8];
    const float* b_proj = (const float*)d_in[9];
    float* out = (float*)d_out;

    // 1. x @ w_init -> query(clip), context  (cols 0..511, ldb=516)
    dim3 g1(512/128, MTOT/128);
    gemm_k<0><<<g1, 256>>>(x, w_init, b_init, nullptr, CDIM, COUT_FULL);

    // 2. gates (cols 512..515), clip to [-1,1]
    gates_k<<<MTOT/8, 256>>>(x, w_init, b_init);

    // 3-5. focal levels: dwconv + gelu + gated accumulate
    dim3 cg(WID/8, HGT/16, BATCH*8);
    dwconv_k<3,0><<<cg, 256>>>(k0);
    dwconv_k<5,1><<<cg, 256>>>(k1);
    dwconv_k<7,2><<<cg, 256>>>(k2);

    // 6. global context: tanh(mean over H,W) * gate3
    dim3 mg(BATCH, 16);
    mean_partial_k<<<mg, 256>>>();
    mean_final_k<<<BATCH, 256>>>();
    add_global_k<<<MTOT, 256>>>();

    // 7. modulator = acc @ w_mod + b_mod; t = clip(q)*clip(mod)
    dim3 g2(256/128, MTOT/128);
    gemm_k<1><<<g2, 256>>>(nullptr, w_mod, b_mod, nullptr, CDIM, CDIM);

    // 8. out = t @ w_proj + b_proj
    gemm_k<2><<<g2, 256>>>(nullptr, w_proj, b_proj, out, CDIM, CDIM);
}

// round 4
// speedup vs baseline: 2.0284x; 2.0284x over previous
#include <cuda_runtime.h>
#include <math.h>
#include <stdint.h>

#define BATCH 32
#define HGT 64
#define WID 64
#define CDIM 256
#define MTOT (BATCH*HGT*WID)   /* 131072 rows */
#define COUT_FULL 516

// ---------------- scratch (device globals: no allocation allowed) -----------
__device__ float g_q   [(size_t)MTOT*CDIM];   // clipped query
__device__ float g_c0  [(size_t)MTOT*CDIM];   // ping
__device__ float g_c1  [(size_t)MTOT*CDIM];   // pong
__device__ float g_acc [(size_t)MTOT*CDIM];   // context_all accumulator
__device__ float g_gates[(size_t)MTOT*4];     // clipped gates
__device__ float g_partial[BATCH*16*CDIM];    // deterministic mean stage 1
__device__ float g_mean[BATCH*CDIM];          // tanh(mean)

__device__ __forceinline__ float gelu_f(float x){
    return 0.5f*x*(1.0f+erff(x*0.70710678118654752440f));
}
__device__ __forceinline__ float clipf(float v, float lim){
    return fminf(fmaxf(v, -lim), lim);
}
__device__ __forceinline__ unsigned f2tf(float f){
    unsigned u; asm("cvt.rna.tf32.f32 %0, %1;" : "=r"(u) : "f"(f)); return u;
}
__device__ __forceinline__ void mma_tf32(float* c, const unsigned* a,
                                         unsigned b0, unsigned b1){
    asm volatile("mma.sync.aligned.m16n8k8.row.col.f32.tf32.tf32.f32 "
        "{%0,%1,%2,%3},{%4,%5,%6,%7},{%8,%9},{%0,%1,%2,%3};"
        : "+f"(c[0]),"+f"(c[1]),"+f"(c[2]),"+f"(c[3])
        : "r"(a[0]),"r"(a[1]),"r"(a[2]),"r"(a[3]),"r"(b0),"r"(b1));
}

// ---------------- tensor-core tf32 GEMM, 128x128 block, K=256 ---------------
// MODE 0: A=x (ext), B=w_init (ldb=516), N=512. cols<256 -> g_q (clip 100),
//         cols>=256 -> g_c0 (context).
// MODE 1: A = g_acc + g_mean*gate3 (fused add_global), B=w_mod, N=256.
//         out g_c0 = clip(v,100) * g_q
// MODE 2: A=g_c0, B=w_proj, N=256. out ext (d_out) = v
template<int MODE>
__global__ __launch_bounds__(256)
void gemm_tc(const float* __restrict__ Aext, const float* __restrict__ Bw,
             const float* __restrict__ bias, float* __restrict__ outext,
             int ldb)
{
    const float* Aptr = (MODE==0) ? Aext : (MODE==1 ? g_acc : g_c0);
    __shared__ unsigned As[128][36];   // row-major, stride 36 (conflict-free frag reads)
    __shared__ unsigned Bs[32][132];   // k-major,  stride 132

    int t    = threadIdx.x;
    int lane = t & 31, wid = t >> 5;
    int wm   = (wid & 3) * 32;        // warp tile 32(M) x 64(N)
    int wn   = (wid >> 2) * 64;
    int qid  = lane >> 2, tid4 = lane & 3;

    int row0 = blockIdx.y * 128;
    int col0 = blockIdx.x * 128;

    int a_c4 = t & 7;     // k-float4 index 0..7
    int a_r  = t >> 3;    // row base 0..31
    int b_c4 = t & 31;    // n-float4 index 0..31
    int b_k  = t >> 5;    // k base 0..7

    float4 aS[4], bS[4];

#define LOAD_TILE(kt)                                                          \
  {                                                                            \
    int kb = (kt)*32;                                                          \
    _Pragma("unroll")                                                          \
    for (int i=0;i<4;i++){                                                     \
      int r = row0 + a_r + 32*i;                                               \
      float4 v = *(const float4*)(Aptr + (size_t)r*CDIM + kb + a_c4*4);        \
      if (MODE==1){                                                            \
        float g3 = g_gates[(size_t)r*4+3];                                     \
        float4 mv = *(const float4*)(g_mean + (r>>12)*CDIM + kb + a_c4*4);     \
        v.x = fmaf(mv.x,g3,v.x); v.y = fmaf(mv.y,g3,v.y);                      \
        v.z = fmaf(mv.z,g3,v.z); v.w = fmaf(mv.w,g3,v.w);                      \
      }                                                                        \
      aS[i]=v;                                                                 \
    }                                                                          \
    _Pragma("unroll")                                                          \
    for (int i=0;i<4;i++)                                                      \
      bS[i] = *(const float4*)(Bw + (size_t)(kb + b_k + 8*i)*ldb               \
                               + col0 + b_c4*4);                               \
  }

    float acc[2][8][4];
    #pragma unroll
    for (int mt=0;mt<2;mt++)
      #pragma unroll
      for (int nt=0;nt<8;nt++)
        #pragma unroll
        for (int j=0;j<4;j++) acc[mt][nt][j] = 0.f;

    LOAD_TILE(0);

    for (int kt = 0; kt < 8; kt++) {
        __syncthreads();
        // stage -> smem (convert to tf32, vectorized 128-bit stores)
        #pragma unroll
        for (int i=0;i<4;i++){
            uint4 u = make_uint4(f2tf(aS[i].x), f2tf(aS[i].y),
                                 f2tf(aS[i].z), f2tf(aS[i].w));
            *(uint4*)&As[a_r + 32*i][a_c4*4] = u;
        }
        #pragma unroll
        for (int i=0;i<4;i++){
            uint4 u = make_uint4(f2tf(bS[i].x), f2tf(bS[i].y),
                                 f2tf(bS[i].z), f2tf(bS[i].w));
            *(uint4*)&Bs[b_k + 8*i][b_c4*4] = u;
        }
        __syncthreads();
        if (kt < 7) LOAD_TILE(kt+1);   // next-tile LDGs overlap compute

        #pragma unroll
        for (int ks=0; ks<32; ks+=8){
            unsigned a[2][4];
            #pragma unroll
            for (int mt=0; mt<2; mt++){
                int r = wm + mt*16 + qid;
                a[mt][0] = As[r    ][ks+tid4];
                a[mt][1] = As[r + 8][ks+tid4];
                a[mt][2] = As[r    ][ks+tid4+4];
                a[mt][3] = As[r + 8][ks+tid4+4];
            }
            #pragma unroll
            for (int nt=0; nt<8; nt++){
                int c = wn + nt*8 + qid;
                unsigned b0 = Bs[ks+tid4  ][c];
                unsigned b1 = Bs[ks+tid4+4][c];
                mma_tf32(acc[0][nt], a[0], b0, b1);
                mma_tf32(acc[1][nt], a[1], b0, b1);
            }
        }
    }
#undef LOAD_TILE

    // epilogue: fragment (mt,nt): rows r, r+8 ; cols c, c+1
    #pragma unroll
    for (int mt=0;mt<2;mt++){
        int r0r = row0 + wm + mt*16 + qid;
        #pragma unroll
        for (int nt=0;nt<8;nt++){
            int c  = col0 + wn + nt*8 + tid4*2;
            float bb0 = bias[c], bb1 = bias[c+1];
            float v0 = acc[mt][nt][0] + bb0;
            float v1 = acc[mt][nt][1] + bb1;
            float v2 = acc[mt][nt][2] + bb0;
            float v3 = acc[mt][nt][3] + bb1;
            if (MODE == 0) {
                if (c < CDIM) {
                    *(float2*)&g_q[(size_t)r0r*CDIM + c] =
                        make_float2(clipf(v0,100.f), clipf(v1,100.f));
                    *(float2*)&g_q[(size_t)(r0r+8)*CDIM + c] =
                        make_float2(clipf(v2,100.f), clipf(v3,100.f));
                } else {
                    int cc = c - CDIM;
                    *(float2*)&g_c0[(size_t)r0r*CDIM + cc] = make_float2(v0, v1);
                    *(float2*)&g_c0[(size_t)(r0r+8)*CDIM + cc] = make_float2(v2, v3);
                }
            } else if (MODE == 1) {
                float q0 = g_q[(size_t)r0r*CDIM + c];
                float q1 = g_q[(size_t)r0r*CDIM + c + 1];
                float q2 = g_q[(size_t)(r0r+8)*CDIM + c];
                float q3 = g_q[(size_t)(r0r+8)*CDIM + c + 1];
                *(float2*)&g_c0[(size_t)r0r*CDIM + c] =
                    make_float2(clipf(v0,100.f)*q0, clipf(v1,100.f)*q1);
                *(float2*)&g_c0[(size_t)(r0r+8)*CDIM + c] =
                    make_float2(clipf(v2,100.f)*q2, clipf(v3,100.f)*q3);
            } else {
                *(float2*)&outext[(size_t)r0r*CDIM + c] = make_float2(v0, v1);
                *(float2*)&outext[(size_t)(r0r+8)*CDIM + c] = make_float2(v2, v3);
            }
        }
    }
}

// ---------------- gates: last 4 columns of w_init, one warp per row ---------
__global__ __launch_bounds__(256)
void gates_k(const float* __restrict__ x, const float* __restrict__ w,
             const float* __restrict__ bias)
{
    int warp = (int)((blockIdx.x * blockDim.x + threadIdx.x) >> 5);
    int lane = threadIdx.x & 31;
    if (warp >= MTOT) return;
    const float* xr = x + (size_t)warp * CDIM;
    float s0=0.f, s1=0.f, s2=0.f, s3=0.f;
    #pragma unroll
    for (int k = lane; k < CDIM; k += 32) {
        float xv = xr[k];
        const float* wr = w + (size_t)k*COUT_FULL + 512;
        s0 = fmaf(xv, wr[0], s0);
        s1 = fmaf(xv, wr[1], s1);
        s2 = fmaf(xv, wr[2], s2);
        s3 = fmaf(xv, wr[3], s3);
    }
    #pragma unroll
    for (int o=16; o; o>>=1) {
        s0 += __shfl_down_sync(0xffffffffu, s0, o);
        s1 += __shfl_down_sync(0xffffffffu, s1, o);
        s2 += __shfl_down_sync(0xffffffffu, s2, o);
        s3 += __shfl_down_sync(0xffffffffu, s3, o);
    }
    if (lane == 0) {
        float* g = g_gates + (size_t)warp*4;
        g[0] = clipf(s0 + bias[512], 1.f);
        g[1] = clipf(s1 + bias[513], 1.f);
        g[2] = clipf(s2 + bias[514], 1.f);
        g[3] = clipf(s3 + bias[515], 1.f);
    }
}

// ---------------- depthwise conv SxS + gelu + gated accumulate --------------
template<int S, int LEVEL>
__global__ __launch_bounds__(256)
void dwconv_k(const float* __restrict__ kern)
{
    constexpr int P = S/2;
    constexpr int TH = 16, TW = 8, CF = 8;
    constexpr int HH = TH + S - 1, HW2 = TW + S - 1;
    const float* in = (LEVEL==1) ? g_c1 : g_c0;
    float* out      = (LEVEL==1) ? g_c0 : g_c1;

    __shared__ float4 sIn[HH*HW2][CF];
    __shared__ float4 sK[S*S][CF];

    int t  = threadIdx.x;
    int w0 = blockIdx.x * TW;
    int h0 = blockIdx.y * TH;
    int z  = blockIdx.z;
    int b  = z >> 3;
    int c0 = (z & 7) * 32;

    for (int i = t; i < S*S*CF; i += 256) {
        int f = i & 7, p = i >> 3;
        sK[p][f] = *(const float4*)(kern + p*CDIM + c0 + f*4);
    }
    for (int i = t; i < HH*HW2*CF; i += 256) {
        int f = i & 7, p = i >> 3;
        int hy = p / HW2, hx = p % HW2;
        int ih = h0 - P + hy, iw = w0 - P + hx;
        float4 v = make_float4(0.f,0.f,0.f,0.f);
        if (ih >= 0 && ih < HGT && iw >= 0 && iw < WID)
            v = *(const float4*)(in + ((size_t)((b*HGT+ih)*WID+iw))*CDIM + c0 + f*4);
        sIn[p][f] = v;
    }
    __syncthreads();

    int f  = t & 7;
    int ox = (t >> 3) & 7;
    int yq = t >> 6;

    float4 acc[4];
    #pragma unroll
    for (int i=0;i<4;i++) acc[i] = make_float4(0.f,0.f,0.f,0.f);

    #pragma unroll
    for (int kw = 0; kw < S; kw++) {
        float4 kv[S];
        #pragma unroll
        for (int kh = 0; kh < S; kh++) kv[kh] = sK[kh*S+kw][f];
        #pragma unroll
        for (int r = 0; r < 4 + S - 1; r++) {
            float4 iv = sIn[(yq*4 + r)*HW2 + ox + kw][f];
            #pragma unroll
            for (int kh = 0; kh < S; kh++) {
                int oy = r - kh;
                if (oy >= 0 && oy < 4) {
                    acc[oy].x = fmaf(iv.x, kv[kh].x, acc[oy].x);
                    acc[oy].y = fmaf(iv.y, kv[kh].y, acc[oy].y);
                    acc[oy].z = fmaf(iv.z, kv[kh].z, acc[oy].z);
                    acc[oy].w = fmaf(iv.w, kv[kh].w, acc[oy].w);
                }
            }
        }
    }

    #pragma unroll
    for (int oy = 0; oy < 4; oy++) {
        float4 v = acc[oy];
        v.x = gelu_f(v.x); v.y = gelu_f(v.y);
        v.z = gelu_f(v.z); v.w = gelu_f(v.w);
        size_t row = (size_t)(b*HGT + h0 + yq*4 + oy)*WID + (w0 + ox);
        size_t idx = row*CDIM + c0 + f*4;
        *(float4*)(out + idx) = v;
        float g = g_gates[row*4 + LEVEL];
        float4 a;
        if (LEVEL == 0) {
            a.x = v.x*g; a.y = v.y*g; a.z = v.z*g; a.w = v.w*g;
        } else {
            float4 prev = *(const float4*)(g_acc + idx);
            a.x = fmaf(v.x, g, prev.x); a.y = fmaf(v.y, g, prev.y);
            a.z = fmaf(v.z, g, prev.z); a.w = fmaf(v.w, g, prev.w);
        }
        *(float4*)(g_acc + idx) = a;
    }
}

// ---------------- spatial mean of final ctx (deterministic 2-stage) ---------
__global__ void mean_partial_k()
{
    int b = blockIdx.x, chunk = blockIdx.y;
    int c = threadIdx.x;
    const float* base = g_c1 + ((size_t)b*4096 + chunk*256)*CDIM + c;
    float s = 0.f;
    #pragma unroll 4
    for (int i = 0; i < 256; i++) s += base[(size_t)i*CDIM];
    g_partial[(b*16 + chunk)*CDIM + c] = s;
}
__global__ void mean_final_k()
{
    int b = blockIdx.x, c = threadIdx.x;
    float s = 0.f;
    #pragma unroll
    for (int i = 0; i < 16; i++) s += g_partial[(b*16 + i)*CDIM + c];
    g_mean[b*CDIM + c] = tanhf(s * (1.0f/4096.0f));
}

// ---------------- launch ----------------------------------------------------
extern "C" void kernel_launch(void* const* d_in, const int* in_sizes, int n_in,
                              void* d_out, int out_size)
{
    const float* x      = (const float*)d_in[0];
    const float* w_init = (const float*)d_in[1];
    const float* b_init = (const float*)d_in[2];
    const float* k0     = (const float*)d_in[3];
    const float* k1     = (const float*)d_in[4];
    const float* k2     = (const float*)d_in[5];
    const float* w_mod  = (const float*)d_in[6];
    const float* b_mod  = (const float*)d_in[7];
    const float* w_proj = (const float*)d_in[8];
    const float* b_proj = (const float*)d_in[9];
    float* out = (float*)d_out;

    // 1. x @ w_init -> query(clip), context  (cols 0..511, ldb=516)
    dim3 g1(512/128, MTOT/128);
    gemm_tc<0><<<g1, 256>>>(x, w_init, b_init, nullptr, COUT_FULL);

    // 2. gates (cols 512..515), clip to [-1,1]
    gates_k<<<MTOT/8, 256>>>(x, w_init, b_init);

    // 3-5. focal levels: dwconv + gelu + gated accumulate
    dim3 cg(WID/8, HGT/16, BATCH*8);
    dwconv_k<3,0><<<cg, 256>>>(k0);
    dwconv_k<5,1><<<cg, 256>>>(k1);
    dwconv_k<7,2><<<cg, 256>>>(k2);

    // 6. global context mean (tanh); add fused into GEMM2's A-load
    dim3 mg(BATCH, 16);
    mean_partial_k<<<mg, 256>>>();
    mean_final_k<<<BATCH, 256>>>();

    // 7. modulator = (acc + mean*g3) @ w_mod + b_mod; t = clip(q)*clip(mod)
    dim3 g2(256/128, MTOT/128);
    gemm_tc<1><<<g2, 256>>>(nullptr, w_mod, b_mod, nullptr, CDIM);

    // 8. out = t @ w_proj + b_proj
    gemm_tc<2><<<g2, 256>>>(nullptr, w_proj, b_proj, out, CDIM);
}

// round 6
// speedup vs baseline: 2.3527x; 1.1599x over previous
#include <cuda_runtime.h>
#include <math.h>
#include <stdint.h>

#define BATCH 32
#define HGT 64
#define WID 64
#define CDIM 256
#define MTOT (BATCH*HGT*WID)   /* 131072 rows */
#define COUT_FULL 516

// ---------------- scratch (device globals: no allocation allowed) -----------
__device__ float g_q   [(size_t)MTOT*CDIM];   // clipped query -> t (in-place)
__device__ float g_c0  [(size_t)MTOT*CDIM];   // context -> ctx3
__device__ float g_c1  [(size_t)MTOT*CDIM];   // ctx1
__device__ float g_acc [(size_t)MTOT*CDIM];   // ctx2
__device__ float g_gates[(size_t)MTOT*4];     // clipped gates
__device__ float g_partial[BATCH*32*CDIM];    // per-tile partial sums of ctx3
__device__ float g_mean[BATCH*CDIM];          // tanh(mean)

__device__ __forceinline__ float gelu_f(float x){
    return 0.5f*x*(1.0f+erff(x*0.70710678118654752440f));
}
__device__ __forceinline__ float clipf(float v, float lim){
    return fminf(fmaxf(v, -lim), lim);
}
__device__ __forceinline__ unsigned f2tf(float f){
    unsigned u; asm("cvt.rna.tf32.f32 %0, %1;" : "=r"(u) : "f"(f)); return u;
}
__device__ __forceinline__ void mma_tf32(float* c, const unsigned* a,
                                         unsigned b0, unsigned b1){
    asm volatile("mma.sync.aligned.m16n8k8.row.col.f32.tf32.tf32.f32 "
        "{%0,%1,%2,%3},{%4,%5,%6,%7},{%8,%9},{%0,%1,%2,%3};"
        : "+f"(c[0]),"+f"(c[1]),"+f"(c[2]),"+f"(c[3])
        : "r"(a[0]),"r"(a[1]),"r"(a[2]),"r"(a[3]),"r"(b0),"r"(b1));
}

#define GEMM_SMEM_WORDS (128*36 + 32*260)   /* 12928 words = 51712 B */

// ---------------- tensor-core tf32 GEMM, 128x256 block, 512 thr, K=256 ------
// MODE 0: A=x, B=w_init (ldb=516), grid.x=2 (cols 0..255 -> g_q clip100,
//         cols 256..511 -> g_c0). Block x==1 also computes gates (cols 512..515)
//         from the As smem tile -> g_gates (clip 1).
// MODE 1: A = ctx1*g0+ctx2*g1+ctx3*g2+mean*g3 (fused), B=w_mod.
//         out: g_q <- clip(v,100) * q   (in-place, element-exact)
// MODE 2: A=g_q (t), B=w_proj. out = ext (d_out).
template<int MODE>
__global__ __launch_bounds__(512)
void gemm_tc(const float* __restrict__ Aext, const float* __restrict__ Bw,
             const float* __restrict__ bias, float* __restrict__ outext,
             int ldb)
{
    extern __shared__ unsigned sh[];
    unsigned (*As)[36]  = (unsigned(*)[36])sh;             // 128 x 36
    unsigned (*Bs)[260] = (unsigned(*)[260])(sh + 128*36); // 32 x 260
    __shared__ float Wg[32][4];                            // gate weights (MODE0)

    const float* Aptr = (MODE==0) ? Aext : (MODE==1 ? (const float*)g_c1
                                                    : (const float*)g_q);
    int t    = threadIdx.x;
    int lane = t & 31, wid = t >> 5;
    int wm   = (wid & 3) * 32;       // warp tile 32(M) x 64(N), 4x4 warps
    int wn   = (wid >> 2) * 64;
    int qid  = lane >> 2, tid4 = lane & 3;

    int row0 = blockIdx.y * 128;
    int col0 = blockIdx.x * 256;

    int a_r  = t >> 3;    // 0..63 ; rows a_r, a_r+64
    int a_c4 = t & 7;     // k-float4 0..7
    int b_k  = t >> 6;    // 0..7  ; ks b_k + 8*i
    int b_c4 = t & 63;    // n-float4 0..63

    float4 aS[2], bS[4];
    float4 gv[2];
    if (MODE==1){
        gv[0] = *(const float4*)&g_gates[(size_t)(row0 + a_r     )*4];
        gv[1] = *(const float4*)&g_gates[(size_t)(row0 + a_r + 64)*4];
    }

#define LOAD_TILE(kt)                                                          \
  {                                                                            \
    int kb = (kt)*32;                                                          \
    _Pragma("unroll")                                                          \
    for (int i=0;i<2;i++){                                                     \
      int r = row0 + a_r + 64*i;                                               \
      size_t off = (size_t)r*CDIM + kb + a_c4*4;                               \
      if (MODE==1){                                                            \
        float4 v1 = *(const float4*)(g_c1  + off);                             \
        float4 v2 = *(const float4*)(g_acc + off);                             \
        float4 v3 = *(const float4*)(g_c0  + off);                             \
        float4 mv = *(const float4*)(g_mean + (size_t)(r>>12)*CDIM             \
                                     + kb + a_c4*4);                           \
        float4 g = gv[i];                                                      \
        float4 v;                                                              \
        v.x = fmaf(mv.x,g.w, fmaf(v3.x,g.z, fmaf(v2.x,g.y, v1.x*g.x)));        \
        v.y = fmaf(mv.y,g.w, fmaf(v3.y,g.z, fmaf(v2.y,g.y, v1.y*g.x)));        \
        v.z = fmaf(mv.z,g.w, fmaf(v3.z,g.z, fmaf(v2.z,g.y, v1.z*g.x)));        \
        v.w = fmaf(mv.w,g.w, fmaf(v3.w,g.z, fmaf(v2.w,g.y, v1.w*g.x)));        \
        aS[i] = v;                                                             \
      } else {                                                                 \
        aS[i] = *(const float4*)(Aptr + off);                                  \
      }                                                                        \
    }                                                                          \
    _Pragma("unroll")                                                          \
    for (int i=0;i<4;i++)                                                      \
      bS[i] = *(const float4*)(Bw + (size_t)(kb + b_k + 8*i)*ldb               \
                               + col0 + b_c4*4);                               \
  }

    float acc[2][8][4];
    #pragma unroll
    for (int mt=0;mt<2;mt++)
      #pragma unroll
      for (int nt=0;nt<8;nt++)
        #pragma unroll
        for (int j=0;j<4;j++) acc[mt][nt][j] = 0.f;

    const bool gate_block = (MODE==0) && (blockIdx.x==1);
    int   g_r = t >> 2, g_c = t & 3;
    float ga  = 0.f;

    LOAD_TILE(0);

    for (int kt = 0; kt < 8; kt++) {
        __syncthreads();
        #pragma unroll
        for (int i=0;i<2;i++){
            uint4 u = make_uint4(f2tf(aS[i].x), f2tf(aS[i].y),
                                 f2tf(aS[i].z), f2tf(aS[i].w));
            *(uint4*)&As[a_r + 64*i][a_c4*4] = u;
        }
        #pragma unroll
        for (int i=0;i<4;i++){
            uint4 u = make_uint4(f2tf(bS[i].x), f2tf(bS[i].y),
                                 f2tf(bS[i].z), f2tf(bS[i].w));
            *(uint4*)&Bs[b_k + 8*i][b_c4*4] = u;
        }
        if (gate_block && t < 128) {
            int k = t >> 2, c = t & 3;
            Wg[k][c] = Bw[(size_t)(kt*32 + k)*ldb + 512 + c];
        }
        __syncthreads();
        if (kt < 7) LOAD_TILE(kt+1);

        if (gate_block) {
            #pragma unroll
            for (int k=0;k<32;k++)
                ga = fmaf(__uint_as_float(As[g_r][k]), Wg[k][g_c], ga);
        }

        #pragma unroll
        for (int ks=0; ks<32; ks+=8){
            unsigned a[2][4];
            #pragma unroll
            for (int mt=0; mt<2; mt++){
                int r = wm + mt*16 + qid;
                a[mt][0] = As[r    ][ks+tid4];
                a[mt][1] = As[r + 8][ks+tid4];
                a[mt][2] = As[r    ][ks+tid4+4];
                a[mt][3] = As[r + 8][ks+tid4+4];
            }
            #pragma unroll
            for (int nt=0; nt<8; nt++){
                int c = wn + nt*8 + qid;
                unsigned b0 = Bs[ks+tid4  ][c];
                unsigned b1 = Bs[ks+tid4+4][c];
                mma_tf32(acc[0][nt], a[0], b0, b1);
                mma_tf32(acc[1][nt], a[1], b0, b1);
            }
        }
    }
#undef LOAD_TILE

    if (gate_block) {
        float g = clipf(ga + bias[512 + g_c], 1.f);
        g_gates[(size_t)(row0 + g_r)*4 + g_c] = g;
    }

    // epilogue: fragment (mt,nt): rows r, r+8 ; cols c, c+1
    #pragma unroll
    for (int mt=0;mt<2;mt++){
        int r0r = row0 + wm + mt*16 + qid;
        #pragma unroll
        for (int nt=0;nt<8;nt++){
            int c  = col0 + wn + nt*8 + tid4*2;
            float bb0 = bias[c], bb1 = bias[c+1];
            float v0 = acc[mt][nt][0] + bb0;
            float v1 = acc[mt][nt][1] + bb1;
            float v2 = acc[mt][nt][2] + bb0;
            float v3 = acc[mt][nt][3] + bb1;
            if (MODE == 0) {
                if (c < CDIM) {
                    *(float2*)&g_q[(size_t)r0r*CDIM + c] =
                        make_float2(clipf(v0,100.f), clipf(v1,100.f));
                    *(float2*)&g_q[(size_t)(r0r+8)*CDIM + c] =
                        make_float2(clipf(v2,100.f), clipf(v3,100.f));
                } else {
                    int cc = c - CDIM;
                    *(float2*)&g_c0[(size_t)r0r*CDIM + cc] = make_float2(v0, v1);
                    *(float2*)&g_c0[(size_t)(r0r+8)*CDIM + cc] = make_float2(v2, v3);
                }
            } else if (MODE == 1) {
                float q0 = g_q[(size_t)r0r*CDIM + c];
                float q1 = g_q[(size_t)r0r*CDIM + c + 1];
                float q2 = g_q[(size_t)(r0r+8)*CDIM + c];
                float q3 = g_q[(size_t)(r0r+8)*CDIM + c + 1];
                *(float2*)&g_q[(size_t)r0r*CDIM + c] =
                    make_float2(clipf(v0,100.f)*q0, clipf(v1,100.f)*q1);
                *(float2*)&g_q[(size_t)(r0r+8)*CDIM + c] =
                    make_float2(clipf(v2,100.f)*q2, clipf(v3,100.f)*q3);
            } else {
                *(float2*)&outext[(size_t)r0r*CDIM + c] = make_float2(v0, v1);
                *(float2*)&outext[(size_t)(r0r+8)*CDIM + c] = make_float2(v2, v3);
            }
        }
    }
}

// ---------------- depthwise conv SxS + gelu (+ fused mean partial on L2) ----
// LEVEL 0: g_c0 -> g_c1   (ctx1)
// LEVEL 1: g_c1 -> g_acc  (ctx2)
// LEVEL 2: g_acc -> g_c0  (ctx3) + per-block spatial partial sums
template<int S, int LEVEL>
__global__ __launch_bounds__(256)
void dwconv_k(const float* __restrict__ kern)
{
    constexpr int P = S/2;
    constexpr int TH = 16, TW = 8, CF = 8;
    constexpr int HH = TH + S - 1, HW2 = TW + S - 1;
    const float* in = (LEVEL==0) ? g_c0 : (LEVEL==1) ? g_c1 : g_acc;
    float* out      = (LEVEL==0) ? g_c1 : (LEVEL==1) ? g_acc : g_c0;

    __shared__ float4 sIn[HH*HW2][CF];
    __shared__ float4 sK[S*S][CF];

    int t  = threadIdx.x;
    int w0 = blockIdx.x * TW;
    int h0 = blockIdx.y * TH;
    int z  = blockIdx.z;
    int b  = z >> 3;
    int c0 = (z & 7) * 32;

    for (int i = t; i < S*S*CF; i += 256) {
        int f = i & 7, p = i >> 3;
        sK[p][f] = *(const float4*)(kern + p*CDIM + c0 + f*4);
    }
    for (int i = t; i < HH*HW2*CF; i += 256) {
        int f = i & 7, p = i >> 3;
        int hy = p / HW2, hx = p % HW2;
        int ih = h0 - P + hy, iw = w0 - P + hx;
        float4 v = make_float4(0.f,0.f,0.f,0.f);
        if (ih >= 0 && ih < HGT && iw >= 0 && iw < WID)
            v = *(const float4*)(in + ((size_t)((b*HGT+ih)*WID+iw))*CDIM + c0 + f*4);
        sIn[p][f] = v;
    }
    __syncthreads();

    int f  = t & 7;
    int ox = (t >> 3) & 7;
    int yq = t >> 6;

    float4 acc[4];
    #pragma unroll
    for (int i=0;i<4;i++) acc[i] = make_float4(0.f,0.f,0.f,0.f);

    #pragma unroll
    for (int kw = 0; kw < S; kw++) {
        float4 kv[S];
        #pragma unroll
        for (int kh = 0; kh < S; kh++) kv[kh] = sK[kh*S+kw][f];
        #pragma unroll
        for (int r = 0; r < 4 + S - 1; r++) {
            float4 iv = sIn[(yq*4 + r)*HW2 + ox + kw][f];
            #pragma unroll
            for (int kh = 0; kh < S; kh++) {
                int oy = r - kh;
                if (oy >= 0 && oy < 4) {
                    acc[oy].x = fmaf(iv.x, kv[kh].x, acc[oy].x);
                    acc[oy].y = fmaf(iv.y, kv[kh].y, acc[oy].y);
                    acc[oy].z = fmaf(iv.z, kv[kh].z, acc[oy].z);
                    acc[oy].w = fmaf(iv.w, kv[kh].w, acc[oy].w);
                }
            }
        }
    }

    float4 s = make_float4(0.f,0.f,0.f,0.f);
    #pragma unroll
    for (int oy = 0; oy < 4; oy++) {
        float4 v = acc[oy];
        v.x = gelu_f(v.x); v.y = gelu_f(v.y);
        v.z = gelu_f(v.z); v.w = gelu_f(v.w);
        size_t row = (size_t)(b*HGT + h0 + yq*4 + oy)*WID + (w0 + ox);
        *(float4*)(out + row*CDIM + c0 + f*4) = v;
        if (LEVEL == 2) {
            s.x += v.x; s.y += v.y; s.z += v.z; s.w += v.w;
        }
    }

    if (LEVEL == 2) {
        // deterministic per-block spatial partial sum (reuse sIn as scratch)
        float4* red = (float4*)&sIn[0][0];
        __syncthreads();           // everyone done reading sIn
        red[t] = s;
        __syncthreads();
        #pragma unroll
        for (int st = 128; st >= 8; st >>= 1) {
            if (t < st) {
                float4 a = red[t], bb = red[t+st];
                red[t] = make_float4(a.x+bb.x, a.y+bb.y, a.z+bb.z, a.w+bb.w);
            }
            __syncthreads();
        }
        if (t < 8) {
            int tile = blockIdx.y * 8 + blockIdx.x;   // 0..31
            *(float4*)&g_partial[((size_t)(b*32 + tile))*CDIM + c0 + t*4] = red[t];
        }
    }
}

// ---------------- final mean: sum 32 tiles, tanh --------------------------
__global__ void mean_final_k()
{
    int b = blockIdx.x, c = threadIdx.x;
    float s = 0.f;
    #pragma unroll
    for (int i = 0; i < 32; i++) s += g_partial[(size_t)(b*32 + i)*CDIM + c];
    g_mean[b*CDIM + c] = tanhf(s * (1.0f/4096.0f));
}

// ---------------- launch ----------------------------------------------------
extern "C" void kernel_launch(void* const* d_in, const int* in_sizes, int n_in,
                              void* d_out, int out_size)
{
    const float* x      = (const float*)d_in[0];
    const float* w_init = (const float*)d_in[1];
    const float* b_init = (const float*)d_in[2];
    const float* k0     = (const float*)d_in[3];
    const float* k1     = (const float*)d_in[4];
    const float* k2     = (const float*)d_in[5];
    const float* w_mod  = (const float*)d_in[6];
    const float* b_mod  = (const float*)d_in[7];
    const float* w_proj = (const float*)d_in[8];
    const float* b_proj = (const float*)d_in[9];
    float* out = (float*)d_out;

    const int smem = GEMM_SMEM_WORDS * 4;
    cudaFuncSetAttribute(gemm_tc<0>, cudaFuncAttributeMaxDynamicSharedMemorySize, smem);
    cudaFuncSetAttribute(gemm_tc<1>, cudaFuncAttributeMaxDynamicSharedMemorySize, smem);
    cudaFuncSetAttribute(gemm_tc<2>, cudaFuncAttributeMaxDynamicSharedMemorySize, smem);

    // 1. x @ w_init -> query(clip)->g_q, context->g_c0, gates->g_gates
    gemm_tc<0><<<dim3(2, MTOT/128), 512, smem>>>(x, w_init, b_init, nullptr, COUT_FULL);

    // 2-4. focal levels (pure conv+gelu; L2 emits mean partials)
    dim3 cg(WID/8, HGT/16, BATCH*8);
    dwconv_k<3,0><<<cg, 256>>>(k0);
    dwconv_k<5,1><<<cg, 256>>>(k1);
    dwconv_k<7,2><<<cg, 256>>>(k2);

    // 5. tanh(mean)
    mean_final_k<<<BATCH, 256>>>();

    // 6. modulator GEMM with fused gated-sum A; t = clip(q)*clip(mod) -> g_q
    gemm_tc<1><<<dim3(1, MTOT/128), 512, smem>>>(nullptr, w_mod, b_mod, nullptr, CDIM);

    // 7. out = t @ w_proj + b_proj
    gemm_tc<2><<<dim3(1, MTOT/128), 512, smem>>>(nullptr, w_proj, b_proj, out, CDIM);
}